// round 1
// baseline (speedup 1.0000x reference)
#include <cuda_runtime.h>
#include <cuda_bf16.h>
#include <cstdint>
#include <cstdio>

// ---------------------------------------------------------------------------
// Problem constants
// ---------------------------------------------------------------------------
#define NUM_HEADS 24
#define HEAD_DIM  128
#define HIDDEN    3072
#define MLPD      12288
#define T_IMG     1536
#define T_TXT     512
#define SEQ_L     2048   // T_IMG + T_TXT

// ---------------------------------------------------------------------------
// Scratch (device globals; allocation-free per harness rules)
// ---------------------------------------------------------------------------
__device__ float g_xm[(size_t)T_IMG * HIDDEN];              // LN+mod output (img or txt, reused)
__device__ float g_qkv_img[(size_t)T_IMG * 3 * HIDDEN];
__device__ float g_qkv_txt[(size_t)T_TXT * 3 * HIDDEN];
__device__ float g_q[(size_t)NUM_HEADS * SEQ_L * HEAD_DIM];
__device__ float g_k[(size_t)NUM_HEADS * SEQ_L * HEAD_DIM];
__device__ float g_vT[(size_t)NUM_HEADS * HEAD_DIM * SEQ_L];
__device__ float g_scores[(size_t)NUM_HEADS * SEQ_L * SEQ_L];   // ~402 MB
__device__ float g_attn[(size_t)SEQ_L * HIDDEN];
__device__ float g_tmp[(size_t)T_IMG * HIDDEN];
__device__ float g_h[(size_t)T_IMG * MLPD];

// ---------------------------------------------------------------------------
// Helpers
// ---------------------------------------------------------------------------
__device__ __forceinline__ float ftf32(float x) {
    uint32_t u;
    asm("cvt.rna.tf32.f32 %0, %1;" : "=r"(u) : "f"(x));
    return __uint_as_float(u);
}

__device__ __forceinline__ void mma_tf32(float* d, const uint32_t* a, const uint32_t* b) {
    asm volatile(
        "mma.sync.aligned.m16n8k8.row.col.f32.tf32.tf32.f32 "
        "{%0,%1,%2,%3}, {%4,%5,%6,%7}, {%8,%9}, {%0,%1,%2,%3};\n"
        : "+f"(d[0]), "+f"(d[1]), "+f"(d[2]), "+f"(d[3])
        : "r"(a[0]), "r"(a[1]), "r"(a[2]), "r"(a[3]), "r"(b[0]), "r"(b[1]));
}

__device__ __forceinline__ float gelu_tanh_f(float x) {
    float x3 = x * x * x;
    return 0.5f * x * (1.0f + tanhf(0.7978845608028654f * (x + 0.044715f * x3)));
}

// ---------------------------------------------------------------------------
// Generic tf32 MMA GEMM:  C[M,N] = act(alpha * A[M,K] @ B[N,K]^T + bias)
// Requirements: M%128==0, N%128==0, K%32==0, all lds %4==0.
// Batched via blockIdx.z with element strides sA, sB, sC.
// ---------------------------------------------------------------------------
#define GBM 128
#define GBN 128
#define GBK 32
#define GLD 36   // BK + 4 pad -> conflict-free fragment loads (36 % 32 == 4)

template<int ACT>
__global__ void __launch_bounds__(256, 1)
gemm_tf32(const float* __restrict__ A, const float* __restrict__ B,
          const float* __restrict__ bias, float* __restrict__ C,
          int K, int lda, int ldb, int ldc,
          long long sA, long long sB, long long sC, float alpha)
{
    extern __shared__ float smem[];
    float* As = smem;                 // [GBM][GLD]
    float* Bs = smem + GBM * GLD;     // [GBN][GLD]

    const int tid  = threadIdx.x;
    const int lane = tid & 31;
    const int warp = tid >> 5;
    const int wm = warp & 1;          // 2 warps in M -> 64 rows each
    const int wn = warp >> 1;         // 4 warps in N -> 32 cols each
    const int g  = lane >> 2;         // group id 0..7
    const int tq = lane & 3;          // thread-in-group 0..3

    const long long bz = blockIdx.z;
    const float* Ab = A + bz * sA + (long long)(blockIdx.y * GBM) * lda;
    const float* Bb = B + bz * sB + (long long)(blockIdx.x * GBN) * ldb;
    float*       Cb = C + bz * sC;

    const int lr = tid >> 3;          // 0..31  (row within 32-row slab)
    const int lc = (tid & 7) * 4;     // 0,4,...,28

    float acc[4][4][4];
#pragma unroll
    for (int a = 0; a < 4; a++)
#pragma unroll
        for (int b = 0; b < 4; b++)
#pragma unroll
            for (int r = 0; r < 4; r++) acc[a][b][r] = 0.0f;

    const int ntiles = K / GBK;

    float4 ra[4], rb[4];
    // prologue: load tile 0 into registers
#pragma unroll
    for (int i = 0; i < 4; i++) {
        ra[i] = *(const float4*)(Ab + (long long)(lr + 32 * i) * lda + lc);
        rb[i] = *(const float4*)(Bb + (long long)(lr + 32 * i) * ldb + lc);
    }

    for (int kt = 0; kt < ntiles; kt++) {
        // stage registers -> smem (convert to tf32 for rounding)
#pragma unroll
        for (int i = 0; i < 4; i++) {
            float4 wa = make_float4(ftf32(ra[i].x), ftf32(ra[i].y), ftf32(ra[i].z), ftf32(ra[i].w));
            *(float4*)(As + (lr + 32 * i) * GLD + lc) = wa;
            float4 wb = make_float4(ftf32(rb[i].x), ftf32(rb[i].y), ftf32(rb[i].z), ftf32(rb[i].w));
            *(float4*)(Bs + (lr + 32 * i) * GLD + lc) = wb;
        }
        __syncthreads();

        // prefetch next tile while computing
        if (kt + 1 < ntiles) {
            const int koff = (kt + 1) * GBK;
#pragma unroll
            for (int i = 0; i < 4; i++) {
                ra[i] = *(const float4*)(Ab + (long long)(lr + 32 * i) * lda + koff + lc);
                rb[i] = *(const float4*)(Bb + (long long)(lr + 32 * i) * ldb + koff + lc);
            }
        }

        const uint32_t* asu = (const uint32_t*)As;
        const uint32_t* bsu = (const uint32_t*)Bs;
#pragma unroll
        for (int kk = 0; kk < GBK; kk += 8) {
            uint32_t af[4][4], bf[4][2];
#pragma unroll
            for (int mi = 0; mi < 4; mi++) {
                int r0 = (wm * 64 + mi * 16 + g) * GLD + kk + tq;
                af[mi][0] = asu[r0];
                af[mi][1] = asu[r0 + 8 * GLD];
                af[mi][2] = asu[r0 + 4];
                af[mi][3] = asu[r0 + 8 * GLD + 4];
            }
#pragma unroll
            for (int ni = 0; ni < 4; ni++) {
                int c0 = (wn * 32 + ni * 8 + g) * GLD + kk + tq;
                bf[ni][0] = bsu[c0];
                bf[ni][1] = bsu[c0 + 4];
            }
#pragma unroll
            for (int mi = 0; mi < 4; mi++)
#pragma unroll
                for (int ni = 0; ni < 4; ni++)
                    mma_tf32(acc[mi][ni], af[mi], bf[ni]);
        }
        __syncthreads();
    }

    // epilogue
    const int mb = blockIdx.y * GBM + wm * 64;
    const int nb = blockIdx.x * GBN + wn * 32;
#pragma unroll
    for (int mi = 0; mi < 4; mi++) {
        int row = mb + mi * 16 + g;
#pragma unroll
        for (int ni = 0; ni < 4; ni++) {
            int col = nb + ni * 8 + 2 * tq;
            float v0 = alpha * acc[mi][ni][0];
            float v1 = alpha * acc[mi][ni][1];
            float v2 = alpha * acc[mi][ni][2];
            float v3 = alpha * acc[mi][ni][3];
            if (bias != nullptr) {
                float b0 = bias[col], b1 = bias[col + 1];
                v0 += b0; v1 += b1; v2 += b0; v3 += b1;
            }
            if (ACT == 1) {
                v0 = gelu_tanh_f(v0); v1 = gelu_tanh_f(v1);
                v2 = gelu_tanh_f(v2); v3 = gelu_tanh_f(v3);
            }
            *(float2*)(Cb + (long long)row * ldc + col)       = make_float2(v0, v1);
            *(float2*)(Cb + (long long)(row + 8) * ldc + col) = make_float2(v2, v3);
        }
    }
}

// ---------------------------------------------------------------------------
// LayerNorm + modulation:  out = shift + (1+scale) * LN(x)  per row of 3072
// mod layout: [0:3072)=shift, [3072:6144)=scale
// ---------------------------------------------------------------------------
__global__ void ln_mod_kernel(const float* __restrict__ x, const float* __restrict__ mod,
                              float* __restrict__ out)
{
    const int t = blockIdx.x;
    const float* xr = x + (size_t)t * HIDDEN;
    float* orow = out + (size_t)t * HIDDEN;

    float s = 0.f, s2 = 0.f;
    for (int c = threadIdx.x; c < HIDDEN; c += 256) {
        float v = xr[c];
        s += v; s2 += v * v;
    }
    const int lane = threadIdx.x & 31, wid = threadIdx.x >> 5;
#pragma unroll
    for (int o = 16; o > 0; o >>= 1) {
        s  += __shfl_xor_sync(0xffffffffu, s, o);
        s2 += __shfl_xor_sync(0xffffffffu, s2, o);
    }
    __shared__ float sh[16];
    if (lane == 0) { sh[wid] = s; sh[8 + wid] = s2; }
    __syncthreads();
    float S = 0.f, S2 = 0.f;
#pragma unroll
    for (int w = 0; w < 8; w++) { S += sh[w]; S2 += sh[8 + w]; }
    float mean = S * (1.0f / HIDDEN);
    float var  = S2 * (1.0f / HIDDEN) - mean * mean;
    float inv  = rsqrtf(var + 1e-6f);

    for (int c = threadIdx.x; c < HIDDEN; c += 256) {
        orow[c] = mod[c] + (1.0f + mod[HIDDEN + c]) * ((xr[c] - mean) * inv);
    }
}

// ---------------------------------------------------------------------------
// Per-(token, head): RMS norm q/k, RoPE, scatter into q/k [h][l][d], vT [h][d][l]
// ---------------------------------------------------------------------------
__global__ void rmsrope_kernel(const float* __restrict__ qkv,
                               const float* __restrict__ q_scale,
                               const float* __restrict__ k_scale,
                               const float* __restrict__ pe,
                               float* __restrict__ qo, float* __restrict__ ko,
                               float* __restrict__ vT, int l_off)
{
    const int t = blockIdx.x, h = blockIdx.y, d = threadIdx.x;
    const int l = l_off + t;
    const float* base = qkv + (size_t)t * (3 * HIDDEN) + h * HEAD_DIM;
    float qv = base[d];
    float kv = base[HIDDEN + d];
    float vv = base[2 * HIDDEN + d];

    const int lane = d & 31, wid = d >> 5;
    float qs = qv * qv, ks = kv * kv;
#pragma unroll
    for (int o = 16; o > 0; o >>= 1) {
        qs += __shfl_xor_sync(0xffffffffu, qs, o);
        ks += __shfl_xor_sync(0xffffffffu, ks, o);
    }
    __shared__ float red[8];
    if (lane == 0) { red[wid] = qs; red[4 + wid] = ks; }
    __syncthreads();
    float qm = (red[0] + red[1] + red[2] + red[3]) * (1.0f / HEAD_DIM);
    float km = (red[4] + red[5] + red[6] + red[7]) * (1.0f / HEAD_DIM);

    float qn = qv * rsqrtf(qm + 1e-6f) * q_scale[d];
    float kn = kv * rsqrtf(km + 1e-6f) * k_scale[d];

    __shared__ float sq[HEAD_DIM], sk[HEAD_DIM];
    sq[d] = qn; sk[d] = kn;
    __syncthreads();

    const int i = d >> 1;
    const float* p4 = pe + ((size_t)l * (HEAD_DIM / 2) + i) * 4;
    float rq, rk;
    if ((d & 1) == 0) {
        rq = p4[0] * sq[d] + p4[1] * sq[d + 1];
        rk = p4[0] * sk[d] + p4[1] * sk[d + 1];
    } else {
        rq = p4[2] * sq[d - 1] + p4[3] * sq[d];
        rk = p4[2] * sk[d - 1] + p4[3] * sk[d];
    }
    size_t qidx = ((size_t)h * SEQ_L + l) * HEAD_DIM + d;
    qo[qidx] = rq;
    ko[qidx] = rk;
    vT[((size_t)h * HEAD_DIM + d) * SEQ_L + l] = vv;
}

// ---------------------------------------------------------------------------
// Row softmax over 2048 columns (scores already scaled by 1/sqrt(d))
// ---------------------------------------------------------------------------
__global__ void softmax_kernel(float* __restrict__ s)
{
    float* p = s + (size_t)blockIdx.x * SEQ_L;
    float vals[8];
    float m = -1e30f;
#pragma unroll
    for (int i = 0; i < 8; i++) {
        vals[i] = p[threadIdx.x + i * 256];
        m = fmaxf(m, vals[i]);
    }
    const int lane = threadIdx.x & 31, wid = threadIdx.x >> 5;
#pragma unroll
    for (int o = 16; o > 0; o >>= 1) m = fmaxf(m, __shfl_xor_sync(0xffffffffu, m, o));
    __shared__ float sh[8];
    if (lane == 0) sh[wid] = m;
    __syncthreads();
    float M = sh[0];
#pragma unroll
    for (int w = 1; w < 8; w++) M = fmaxf(M, sh[w]);
    __syncthreads();

    float sum = 0.f;
#pragma unroll
    for (int i = 0; i < 8; i++) {
        vals[i] = __expf(vals[i] - M);
        sum += vals[i];
    }
#pragma unroll
    for (int o = 16; o > 0; o >>= 1) sum += __shfl_xor_sync(0xffffffffu, sum, o);
    if (lane == 0) sh[wid] = sum;
    __syncthreads();
    float S = 0.f;
#pragma unroll
    for (int w = 0; w < 8; w++) S += sh[w];
    float inv = 1.0f / S;
#pragma unroll
    for (int i = 0; i < 8; i++) p[threadIdx.x + i * 256] = vals[i] * inv;
}

// ---------------------------------------------------------------------------
// Gated residual: out = base + gate[c] * delta   (optional final clip)
// ---------------------------------------------------------------------------
template<bool CLIP>
__global__ void residual_kernel(const float* __restrict__ base, const float* __restrict__ delta,
                                const float* __restrict__ gate, float* __restrict__ out, int n)
{
    for (int i = blockIdx.x * blockDim.x + threadIdx.x; i < n; i += gridDim.x * blockDim.x) {
        float v = base[i] + gate[i % HIDDEN] * delta[i];
        if (CLIP) v = fminf(fmaxf(v, -65504.0f), 65504.0f);
        out[i] = v;
    }
}

// ---------------------------------------------------------------------------
// Host launcher
// ---------------------------------------------------------------------------
static void launch_gemm(const float* A, const float* B, const float* bias, float* C,
                        int M, int N, int K, int lda, int ldb, int ldc,
                        long long sA, long long sB, long long sC,
                        int batch, float alpha, int act)
{
    dim3 grid(N / GBN, M / GBM, batch), block(256);
    size_t smem = (size_t)(GBM * GLD + GBN * GLD) * sizeof(float);   // 36864 B
    if (act == 0)
        gemm_tf32<0><<<grid, block, smem>>>(A, B, bias, C, K, lda, ldb, ldc, sA, sB, sC, alpha);
    else
        gemm_tf32<1><<<grid, block, smem>>>(A, B, bias, C, K, lda, ldb, ldc, sA, sB, sC, alpha);
}

extern "C" void kernel_launch(void* const* d_in, const int* in_sizes, int n_in,
                              void* d_out, int out_size)
{
    const float* img         = (const float*)d_in[0];
    const float* txt         = (const float*)d_in[1];
    const float* img_mod1    = (const float*)d_in[2];
    const float* img_mod2    = (const float*)d_in[3];
    const float* txt_mod1    = (const float*)d_in[4];
    const float* txt_mod2    = (const float*)d_in[5];
    const float* img_qkv_w   = (const float*)d_in[6];
    const float* img_qkv_b   = (const float*)d_in[7];
    const float* img_q_scale = (const float*)d_in[8];
    const float* img_k_scale = (const float*)d_in[9];
    const float* img_proj_w  = (const float*)d_in[10];
    const float* img_proj_b  = (const float*)d_in[11];
    const float* img_mlp_w1  = (const float*)d_in[12];
    const float* img_mlp_b1  = (const float*)d_in[13];
    const float* img_mlp_w2  = (const float*)d_in[14];
    const float* img_mlp_b2  = (const float*)d_in[15];
    const float* txt_qkv_w   = (const float*)d_in[16];
    const float* txt_qkv_b   = (const float*)d_in[17];
    const float* txt_q_scale = (const float*)d_in[18];
    const float* txt_k_scale = (const float*)d_in[19];
    const float* txt_proj_w  = (const float*)d_in[20];
    const float* txt_proj_b  = (const float*)d_in[21];
    const float* txt_mlp_w1  = (const float*)d_in[22];
    const float* txt_mlp_b1  = (const float*)d_in[23];
    const float* txt_mlp_w2  = (const float*)d_in[24];
    const float* txt_mlp_b2  = (const float*)d_in[25];
    const float* pe          = (const float*)d_in[26];

    float *xm, *qkv_i, *qkv_t, *q, *k, *vT, *scores, *attn, *tmp, *hbuf;
    cudaGetSymbolAddress((void**)&xm, g_xm);
    cudaGetSymbolAddress((void**)&qkv_i, g_qkv_img);
    cudaGetSymbolAddress((void**)&qkv_t, g_qkv_txt);
    cudaGetSymbolAddress((void**)&q, g_q);
    cudaGetSymbolAddress((void**)&k, g_k);
    cudaGetSymbolAddress((void**)&vT, g_vT);
    cudaGetSymbolAddress((void**)&scores, g_scores);
    cudaGetSymbolAddress((void**)&attn, g_attn);
    cudaGetSymbolAddress((void**)&tmp, g_tmp);
    cudaGetSymbolAddress((void**)&hbuf, g_h);

    float* out_img = (float*)d_out;
    float* out_txt = out_img + (size_t)T_IMG * HIDDEN;

    const float attn_scale = 0.08838834764831845f;  // 1/sqrt(128)

    // ---- QKV for both streams ----
    ln_mod_kernel<<<T_IMG, 256>>>(img, img_mod1, xm);
    launch_gemm(xm, img_qkv_w, img_qkv_b, qkv_i, T_IMG, 3 * HIDDEN, HIDDEN,
                HIDDEN, HIDDEN, 3 * HIDDEN, 0, 0, 0, 1, 1.0f, 0);
    ln_mod_kernel<<<T_TXT, 256>>>(txt, txt_mod1, xm);
    launch_gemm(xm, txt_qkv_w, txt_qkv_b, qkv_t, T_TXT, 3 * HIDDEN, HIDDEN,
                HIDDEN, HIDDEN, 3 * HIDDEN, 0, 0, 0, 1, 1.0f, 0);

    // ---- RMS norm + RoPE + scatter (txt occupies l in [0,512), img [512,2048)) ----
    rmsrope_kernel<<<dim3(T_TXT, NUM_HEADS), HEAD_DIM>>>(qkv_t, txt_q_scale, txt_k_scale, pe, q, k, vT, 0);
    rmsrope_kernel<<<dim3(T_IMG, NUM_HEADS), HEAD_DIM>>>(qkv_i, img_q_scale, img_k_scale, pe, q, k, vT, T_TXT);

    // ---- Attention: scores = (Q K^T)/sqrt(d), softmax, attn = P V ----
    launch_gemm(q, k, nullptr, scores, SEQ_L, SEQ_L, HEAD_DIM,
                HEAD_DIM, HEAD_DIM, SEQ_L,
                (long long)SEQ_L * HEAD_DIM, (long long)SEQ_L * HEAD_DIM,
                (long long)SEQ_L * SEQ_L, NUM_HEADS, attn_scale, 0);
    softmax_kernel<<<NUM_HEADS * SEQ_L, 256>>>(scores);
    launch_gemm(scores, vT, nullptr, attn, SEQ_L, HEAD_DIM, SEQ_L,
                SEQ_L, SEQ_L, HIDDEN,
                (long long)SEQ_L * SEQ_L, (long long)HEAD_DIM * SEQ_L,
                (long long)HEAD_DIM, NUM_HEADS, 1.0f, 0);

    // ---- Attention projections + gated residuals ----
    launch_gemm(attn + (size_t)T_TXT * HIDDEN, img_proj_w, img_proj_b, tmp,
                T_IMG, HIDDEN, HIDDEN, HIDDEN, HIDDEN, HIDDEN, 0, 0, 0, 1, 1.0f, 0);
    residual_kernel<false><<<4096, 256>>>(img, tmp, img_mod1 + 2 * HIDDEN, out_img, T_IMG * HIDDEN);

    launch_gemm(attn, txt_proj_w, txt_proj_b, tmp,
                T_TXT, HIDDEN, HIDDEN, HIDDEN, HIDDEN, HIDDEN, 0, 0, 0, 1, 1.0f, 0);
    residual_kernel<false><<<2048, 256>>>(txt, tmp, txt_mod1 + 2 * HIDDEN, out_txt, T_TXT * HIDDEN);

    // ---- img MLP ----
    ln_mod_kernel<<<T_IMG, 256>>>(out_img, img_mod2, xm);
    launch_gemm(xm, img_mlp_w1, img_mlp_b1, hbuf, T_IMG, MLPD, HIDDEN,
                HIDDEN, HIDDEN, MLPD, 0, 0, 0, 1, 1.0f, 1);
    launch_gemm(hbuf, img_mlp_w2, img_mlp_b2, tmp, T_IMG, HIDDEN, MLPD,
                MLPD, MLPD, HIDDEN, 0, 0, 0, 1, 1.0f, 0);
    residual_kernel<false><<<4096, 256>>>(out_img, tmp, img_mod2 + 2 * HIDDEN, out_img, T_IMG * HIDDEN);

    // ---- txt MLP (final residual fused with clip) ----
    ln_mod_kernel<<<T_TXT, 256>>>(out_txt, txt_mod2, xm);
    launch_gemm(xm, txt_mlp_w1, txt_mlp_b1, hbuf, T_TXT, MLPD, HIDDEN,
                HIDDEN, HIDDEN, MLPD, 0, 0, 0, 1, 1.0f, 1);
    launch_gemm(hbuf, txt_mlp_w2, txt_mlp_b2, tmp, T_TXT, HIDDEN, MLPD,
                MLPD, MLPD, HIDDEN, 0, 0, 0, 1, 1.0f, 0);
    residual_kernel<true><<<2048, 256>>>(out_txt, tmp, txt_mod2 + 2 * HIDDEN, out_txt, T_TXT * HIDDEN);
}

// round 2
// speedup vs baseline: 1.2344x; 1.2344x over previous
#include <cuda_runtime.h>
#include <cuda_bf16.h>
#include <cstdint>
#include <cstdio>

// ---------------------------------------------------------------------------
// Problem constants
// ---------------------------------------------------------------------------
#define NUM_HEADS 24
#define HEAD_DIM  128
#define HIDDEN    3072
#define MLPD      12288
#define T_IMG     1536
#define T_TXT     512
#define SEQ_L     2048   // T_IMG + T_TXT

// ---------------------------------------------------------------------------
// Scratch (device globals; allocation-free per harness rules)
// ---------------------------------------------------------------------------
__device__ float g_xm[(size_t)T_IMG * HIDDEN];
__device__ float g_qkv_img[(size_t)T_IMG * 3 * HIDDEN];
__device__ float g_qkv_txt[(size_t)T_TXT * 3 * HIDDEN];
__device__ float g_q[(size_t)NUM_HEADS * SEQ_L * HEAD_DIM];
__device__ float g_k[(size_t)NUM_HEADS * SEQ_L * HEAD_DIM];
__device__ float g_vT[(size_t)NUM_HEADS * HEAD_DIM * SEQ_L];
__device__ float g_scores[(size_t)NUM_HEADS * SEQ_L * SEQ_L];   // ~402 MB
__device__ float g_attn[(size_t)SEQ_L * HIDDEN];
__device__ float g_tmp[(size_t)T_IMG * HIDDEN];
__device__ float g_h[(size_t)T_IMG * MLPD];

// ---------------------------------------------------------------------------
// Helpers
// ---------------------------------------------------------------------------
__device__ __forceinline__ void mma_tf32(float* d, const uint32_t* a, const uint32_t* b) {
    asm volatile(
        "mma.sync.aligned.m16n8k8.row.col.f32.tf32.tf32.f32 "
        "{%0,%1,%2,%3}, {%4,%5,%6,%7}, {%8,%9}, {%0,%1,%2,%3};\n"
        : "+f"(d[0]), "+f"(d[1]), "+f"(d[2]), "+f"(d[3])
        : "r"(a[0]), "r"(a[1]), "r"(a[2]), "r"(a[3]), "r"(b[0]), "r"(b[1]));
}

__device__ __forceinline__ void cp_async16(uint32_t saddr, const float* gaddr) {
    asm volatile("cp.async.ca.shared.global [%0], [%1], 16;\n" :: "r"(saddr), "l"(gaddr));
}
__device__ __forceinline__ void cp_commit() {
    asm volatile("cp.async.commit_group;\n" ::: "memory");
}
template<int N>
__device__ __forceinline__ void cp_wait() {
    asm volatile("cp.async.wait_group %0;\n" :: "n"(N) : "memory");
}

__device__ __forceinline__ float gelu_tanh_f(float x) {
    float x3 = x * x * x;
    return 0.5f * x * (1.0f + tanhf(0.7978845608028654f * (x + 0.044715f * x3)));
}

// ---------------------------------------------------------------------------
// Generic tf32 MMA GEMM with 3-stage cp.async pipeline:
//   C[M,N] = act(alpha * A[M,K] @ B[N,K]^T + bias)
// Requirements: M%128==0, N%128==0, K%32==0, all lds %4==0.
// Batched via blockIdx.z with element strides sA, sB, sC.
// fp32 inputs are consumed as tf32 by truncation (no explicit cvt).
// ---------------------------------------------------------------------------
#define GBM 128
#define GBN 128
#define GBK 32
#define GLD 36                      // 32 + 4 pad floats (row stride 144B, 16B-aligned)
#define NSTG 3
#define STAGE_F (2 * GBM * GLD)     // floats per stage (A tile + B tile) = 9216

template<int ACT>
__global__ void __launch_bounds__(256, 1)
gemm_tf32(const float* __restrict__ A, const float* __restrict__ B,
          const float* __restrict__ bias, float* __restrict__ C,
          int K, int lda, int ldb, int ldc,
          long long sA, long long sB, long long sC, float alpha)
{
    extern __shared__ float smem[];
    const uint32_t sbase = (uint32_t)__cvta_generic_to_shared(smem);

    const int tid  = threadIdx.x;
    const int lane = tid & 31;
    const int warp = tid >> 5;
    const int wm = warp & 1;          // 2 warps in M -> 64 rows each
    const int wn = warp >> 1;         // 4 warps in N -> 32 cols each
    const int g  = lane >> 2;         // 0..7
    const int tq = lane & 3;          // 0..3

    const long long bz = blockIdx.z;
    const float* Ab = A + bz * sA + (long long)(blockIdx.y * GBM) * lda;
    const float* Bb = B + bz * sB + (long long)(blockIdx.x * GBN) * ldb;
    float*       Cb = C + bz * sC;

    // cp.async mapping: 1024 16B-chunks per matrix per stage; 4 per thread.
    const int crow[4] = { (tid + 0) >> 3, (tid + 256) >> 3, (tid + 512) >> 3, (tid + 768) >> 3 };
    const int ccol = (tid & 7) * 4;    // float offset within row

    const int ntiles = K / GBK;

    auto load_stage = [&](int stage, int kt) {
        const uint32_t sa = sbase + (uint32_t)(stage * STAGE_F) * 4u;
        const uint32_t sb = sa + (uint32_t)(GBM * GLD) * 4u;
        const int koff = kt * GBK + ccol;
#pragma unroll
        for (int i = 0; i < 4; i++) {
            int r = crow[i];
            cp_async16(sa + (uint32_t)(r * GLD + ccol) * 4u, Ab + (long long)r * lda + koff);
            cp_async16(sb + (uint32_t)(r * GLD + ccol) * 4u, Bb + (long long)r * ldb + koff);
        }
    };

    float acc[4][4][4];
#pragma unroll
    for (int a = 0; a < 4; a++)
#pragma unroll
        for (int b = 0; b < 4; b++)
#pragma unroll
            for (int r = 0; r < 4; r++) acc[a][b][r] = 0.0f;

    // prologue: fill NSTG-1 stages
#pragma unroll
    for (int s = 0; s < NSTG - 1; s++) {
        if (s < ntiles) load_stage(s, s);
        cp_commit();
    }

    for (int kt = 0; kt < ntiles; kt++) {
        cp_wait<NSTG - 2>();
        __syncthreads();

        // issue loads for stage kt + NSTG - 1 (buffer consumed at kt-1)
        if (kt + NSTG - 1 < ntiles) load_stage((kt + NSTG - 1) % NSTG, kt + NSTG - 1);
        cp_commit();

        const int stage = kt % NSTG;
        const uint32_t* asu = (const uint32_t*)(smem + stage * STAGE_F);
        const uint32_t* bsu = asu + GBM * GLD;

#pragma unroll
        for (int kk = 0; kk < GBK; kk += 8) {
            uint32_t af[4][4], bf[4][2];
#pragma unroll
            for (int mi = 0; mi < 4; mi++) {
                int r0 = (wm * 64 + mi * 16 + g) * GLD + kk + tq;
                af[mi][0] = asu[r0];
                af[mi][1] = asu[r0 + 8 * GLD];
                af[mi][2] = asu[r0 + 4];
                af[mi][3] = asu[r0 + 8 * GLD + 4];
            }
#pragma unroll
            for (int ni = 0; ni < 4; ni++) {
                int c0 = (wn * 32 + ni * 8 + g) * GLD + kk + tq;
                bf[ni][0] = bsu[c0];
                bf[ni][1] = bsu[c0 + 4];
            }
#pragma unroll
            for (int mi = 0; mi < 4; mi++)
#pragma unroll
                for (int ni = 0; ni < 4; ni++)
                    mma_tf32(acc[mi][ni], af[mi], bf[ni]);
        }
    }

    // epilogue
    const int mb = blockIdx.y * GBM + wm * 64;
    const int nb = blockIdx.x * GBN + wn * 32;
#pragma unroll
    for (int mi = 0; mi < 4; mi++) {
        int row = mb + mi * 16 + g;
#pragma unroll
        for (int ni = 0; ni < 4; ni++) {
            int col = nb + ni * 8 + 2 * tq;
            float v0 = alpha * acc[mi][ni][0];
            float v1 = alpha * acc[mi][ni][1];
            float v2 = alpha * acc[mi][ni][2];
            float v3 = alpha * acc[mi][ni][3];
            if (bias != nullptr) {
                float b0 = bias[col], b1 = bias[col + 1];
                v0 += b0; v1 += b1; v2 += b0; v3 += b1;
            }
            if (ACT == 1) {
                v0 = gelu_tanh_f(v0); v1 = gelu_tanh_f(v1);
                v2 = gelu_tanh_f(v2); v3 = gelu_tanh_f(v3);
            }
            *(float2*)(Cb + (long long)row * ldc + col)       = make_float2(v0, v1);
            *(float2*)(Cb + (long long)(row + 8) * ldc + col) = make_float2(v2, v3);
        }
    }
}

// ---------------------------------------------------------------------------
// LayerNorm + modulation:  out = shift + (1+scale) * LN(x)  per row of 3072
// ---------------------------------------------------------------------------
__global__ void ln_mod_kernel(const float* __restrict__ x, const float* __restrict__ mod,
                              float* __restrict__ out)
{
    const int t = blockIdx.x;
    const float* xr = x + (size_t)t * HIDDEN;
    float* orow = out + (size_t)t * HIDDEN;

    float s = 0.f, s2 = 0.f;
    for (int c = threadIdx.x; c < HIDDEN; c += 256) {
        float v = xr[c];
        s += v; s2 += v * v;
    }
    const int lane = threadIdx.x & 31, wid = threadIdx.x >> 5;
#pragma unroll
    for (int o = 16; o > 0; o >>= 1) {
        s  += __shfl_xor_sync(0xffffffffu, s, o);
        s2 += __shfl_xor_sync(0xffffffffu, s2, o);
    }
    __shared__ float sh[16];
    if (lane == 0) { sh[wid] = s; sh[8 + wid] = s2; }
    __syncthreads();
    float S = 0.f, S2 = 0.f;
#pragma unroll
    for (int w = 0; w < 8; w++) { S += sh[w]; S2 += sh[8 + w]; }
    float mean = S * (1.0f / HIDDEN);
    float var  = S2 * (1.0f / HIDDEN) - mean * mean;
    float inv  = rsqrtf(var + 1e-6f);

    for (int c = threadIdx.x; c < HIDDEN; c += 256) {
        orow[c] = mod[c] + (1.0f + mod[HIDDEN + c]) * ((xr[c] - mean) * inv);
    }
}

// ---------------------------------------------------------------------------
// Per-(token, head): RMS norm q/k, RoPE, scatter into q/k [h][l][d], vT [h][d][l]
// ---------------------------------------------------------------------------
__global__ void rmsrope_kernel(const float* __restrict__ qkv,
                               const float* __restrict__ q_scale,
                               const float* __restrict__ k_scale,
                               const float* __restrict__ pe,
                               float* __restrict__ qo, float* __restrict__ ko,
                               float* __restrict__ vT, int l_off)
{
    const int t = blockIdx.x, h = blockIdx.y, d = threadIdx.x;
    const int l = l_off + t;
    const float* base = qkv + (size_t)t * (3 * HIDDEN) + h * HEAD_DIM;
    float qv = base[d];
    float kv = base[HIDDEN + d];
    float vv = base[2 * HIDDEN + d];

    const int lane = d & 31, wid = d >> 5;
    float qs = qv * qv, ks = kv * kv;
#pragma unroll
    for (int o = 16; o > 0; o >>= 1) {
        qs += __shfl_xor_sync(0xffffffffu, qs, o);
        ks += __shfl_xor_sync(0xffffffffu, ks, o);
    }
    __shared__ float red[8];
    if (lane == 0) { red[wid] = qs; red[4 + wid] = ks; }
    __syncthreads();
    float qm = (red[0] + red[1] + red[2] + red[3]) * (1.0f / HEAD_DIM);
    float km = (red[4] + red[5] + red[6] + red[7]) * (1.0f / HEAD_DIM);

    float qn = qv * rsqrtf(qm + 1e-6f) * q_scale[d];
    float kn = kv * rsqrtf(km + 1e-6f) * k_scale[d];

    __shared__ float sq[HEAD_DIM], sk[HEAD_DIM];
    sq[d] = qn; sk[d] = kn;
    __syncthreads();

    const int i = d >> 1;
    const float* p4 = pe + ((size_t)l * (HEAD_DIM / 2) + i) * 4;
    float rq, rk;
    if ((d & 1) == 0) {
        rq = p4[0] * sq[d] + p4[1] * sq[d + 1];
        rk = p4[0] * sk[d] + p4[1] * sk[d + 1];
    } else {
        rq = p4[2] * sq[d - 1] + p4[3] * sq[d];
        rk = p4[2] * sk[d - 1] + p4[3] * sk[d];
    }
    size_t qidx = ((size_t)h * SEQ_L + l) * HEAD_DIM + d;
    qo[qidx] = rq;
    ko[qidx] = rk;
    vT[((size_t)h * HEAD_DIM + d) * SEQ_L + l] = vv;
}

// ---------------------------------------------------------------------------
// Row softmax over 2048 columns
// ---------------------------------------------------------------------------
__global__ void softmax_kernel(float* __restrict__ s)
{
    float* p = s + (size_t)blockIdx.x * SEQ_L;
    float vals[8];
    float m = -1e30f;
#pragma unroll
    for (int i = 0; i < 8; i++) {
        vals[i] = p[threadIdx.x + i * 256];
        m = fmaxf(m, vals[i]);
    }
    const int lane = threadIdx.x & 31, wid = threadIdx.x >> 5;
#pragma unroll
    for (int o = 16; o > 0; o >>= 1) m = fmaxf(m, __shfl_xor_sync(0xffffffffu, m, o));
    __shared__ float sh[8];
    if (lane == 0) sh[wid] = m;
    __syncthreads();
    float M = sh[0];
#pragma unroll
    for (int w = 1; w < 8; w++) M = fmaxf(M, sh[w]);
    __syncthreads();

    float sum = 0.f;
#pragma unroll
    for (int i = 0; i < 8; i++) {
        vals[i] = __expf(vals[i] - M);
        sum += vals[i];
    }
#pragma unroll
    for (int o = 16; o > 0; o >>= 1) sum += __shfl_xor_sync(0xffffffffu, sum, o);
    if (lane == 0) sh[wid] = sum;
    __syncthreads();
    float S = 0.f;
#pragma unroll
    for (int w = 0; w < 8; w++) S += sh[w];
    float inv = 1.0f / S;
#pragma unroll
    for (int i = 0; i < 8; i++) p[threadIdx.x + i * 256] = vals[i] * inv;
}

// ---------------------------------------------------------------------------
// Gated residual: out = base + gate[c] * delta   (optional final clip)
// ---------------------------------------------------------------------------
template<bool CLIP>
__global__ void residual_kernel(const float* __restrict__ base, const float* __restrict__ delta,
                                const float* __restrict__ gate, float* __restrict__ out, int n)
{
    for (int i = blockIdx.x * blockDim.x + threadIdx.x; i < n; i += gridDim.x * blockDim.x) {
        float v = base[i] + gate[i % HIDDEN] * delta[i];
        if (CLIP) v = fminf(fmaxf(v, -65504.0f), 65504.0f);
        out[i] = v;
    }
}

// ---------------------------------------------------------------------------
// Host launcher
// ---------------------------------------------------------------------------
#define GEMM_SMEM (NSTG * STAGE_F * sizeof(float))   // 110592 bytes

static void launch_gemm(const float* A, const float* B, const float* bias, float* C,
                        int M, int N, int K, int lda, int ldb, int ldc,
                        long long sA, long long sB, long long sC,
                        int batch, float alpha, int act)
{
    dim3 grid(N / GBN, M / GBM, batch), block(256);
    if (act == 0)
        gemm_tf32<0><<<grid, block, GEMM_SMEM>>>(A, B, bias, C, K, lda, ldb, ldc, sA, sB, sC, alpha);
    else
        gemm_tf32<1><<<grid, block, GEMM_SMEM>>>(A, B, bias, C, K, lda, ldb, ldc, sA, sB, sC, alpha);
}

extern "C" void kernel_launch(void* const* d_in, const int* in_sizes, int n_in,
                              void* d_out, int out_size)
{
    static bool attr_done = false;
    if (!attr_done) {
        cudaFuncSetAttribute(gemm_tf32<0>, cudaFuncAttributeMaxDynamicSharedMemorySize, GEMM_SMEM);
        cudaFuncSetAttribute(gemm_tf32<1>, cudaFuncAttributeMaxDynamicSharedMemorySize, GEMM_SMEM);
        attr_done = true;
    }

    const float* img         = (const float*)d_in[0];
    const float* txt         = (const float*)d_in[1];
    const float* img_mod1    = (const float*)d_in[2];
    const float* img_mod2    = (const float*)d_in[3];
    const float* txt_mod1    = (const float*)d_in[4];
    const float* txt_mod2    = (const float*)d_in[5];
    const float* img_qkv_w   = (const float*)d_in[6];
    const float* img_qkv_b   = (const float*)d_in[7];
    const float* img_q_scale = (const float*)d_in[8];
    const float* img_k_scale = (const float*)d_in[9];
    const float* img_proj_w  = (const float*)d_in[10];
    const float* img_proj_b  = (const float*)d_in[11];
    const float* img_mlp_w1  = (const float*)d_in[12];
    const float* img_mlp_b1  = (const float*)d_in[13];
    const float* img_mlp_w2  = (const float*)d_in[14];
    const float* img_mlp_b2  = (const float*)d_in[15];
    const float* txt_qkv_w   = (const float*)d_in[16];
    const float* txt_qkv_b   = (const float*)d_in[17];
    const float* txt_q_scale = (const float*)d_in[18];
    const float* txt_k_scale = (const float*)d_in[19];
    const float* txt_proj_w  = (const float*)d_in[20];
    const float* txt_proj_b  = (const float*)d_in[21];
    const float* txt_mlp_w1  = (const float*)d_in[22];
    const float* txt_mlp_b1  = (const float*)d_in[23];
    const float* txt_mlp_w2  = (const float*)d_in[24];
    const float* txt_mlp_b2  = (const float*)d_in[25];
    const float* pe          = (const float*)d_in[26];

    float *xm, *qkv_i, *qkv_t, *q, *k, *vT, *scores, *attn, *tmp, *hbuf;
    cudaGetSymbolAddress((void**)&xm, g_xm);
    cudaGetSymbolAddress((void**)&qkv_i, g_qkv_img);
    cudaGetSymbolAddress((void**)&qkv_t, g_qkv_txt);
    cudaGetSymbolAddress((void**)&q, g_q);
    cudaGetSymbolAddress((void**)&k, g_k);
    cudaGetSymbolAddress((void**)&vT, g_vT);
    cudaGetSymbolAddress((void**)&scores, g_scores);
    cudaGetSymbolAddress((void**)&attn, g_attn);
    cudaGetSymbolAddress((void**)&tmp, g_tmp);
    cudaGetSymbolAddress((void**)&hbuf, g_h);

    float* out_img = (float*)d_out;
    float* out_txt = out_img + (size_t)T_IMG * HIDDEN;

    const float attn_scale = 0.08838834764831845f;  // 1/sqrt(128)

    // ---- QKV for both streams ----
    ln_mod_kernel<<<T_IMG, 256>>>(img, img_mod1, xm);
    launch_gemm(xm, img_qkv_w, img_qkv_b, qkv_i, T_IMG, 3 * HIDDEN, HIDDEN,
                HIDDEN, HIDDEN, 3 * HIDDEN, 0, 0, 0, 1, 1.0f, 0);
    ln_mod_kernel<<<T_TXT, 256>>>(txt, txt_mod1, xm);
    launch_gemm(xm, txt_qkv_w, txt_qkv_b, qkv_t, T_TXT, 3 * HIDDEN, HIDDEN,
                HIDDEN, HIDDEN, 3 * HIDDEN, 0, 0, 0, 1, 1.0f, 0);

    // ---- RMS norm + RoPE + scatter (txt tokens first: l in [0,512), img [512,2048)) ----
    rmsrope_kernel<<<dim3(T_TXT, NUM_HEADS), HEAD_DIM>>>(qkv_t, txt_q_scale, txt_k_scale, pe, q, k, vT, 0);
    rmsrope_kernel<<<dim3(T_IMG, NUM_HEADS), HEAD_DIM>>>(qkv_i, img_q_scale, img_k_scale, pe, q, k, vT, T_TXT);

    // ---- Attention ----
    launch_gemm(q, k, nullptr, scores, SEQ_L, SEQ_L, HEAD_DIM,
                HEAD_DIM, HEAD_DIM, SEQ_L,
                (long long)SEQ_L * HEAD_DIM, (long long)SEQ_L * HEAD_DIM,
                (long long)SEQ_L * SEQ_L, NUM_HEADS, attn_scale, 0);
    softmax_kernel<<<NUM_HEADS * SEQ_L, 256>>>(scores);
    launch_gemm(scores, vT, nullptr, attn, SEQ_L, HEAD_DIM, SEQ_L,
                SEQ_L, SEQ_L, HIDDEN,
                (long long)SEQ_L * SEQ_L, (long long)HEAD_DIM * SEQ_L,
                (long long)HEAD_DIM, NUM_HEADS, 1.0f, 0);

    // ---- Attention projections + gated residuals ----
    launch_gemm(attn + (size_t)T_TXT * HIDDEN, img_proj_w, img_proj_b, tmp,
                T_IMG, HIDDEN, HIDDEN, HIDDEN, HIDDEN, HIDDEN, 0, 0, 0, 1, 1.0f, 0);
    residual_kernel<false><<<4096, 256>>>(img, tmp, img_mod1 + 2 * HIDDEN, out_img, T_IMG * HIDDEN);

    launch_gemm(attn, txt_proj_w, txt_proj_b, tmp,
                T_TXT, HIDDEN, HIDDEN, HIDDEN, HIDDEN, HIDDEN, 0, 0, 0, 1, 1.0f, 0);
    residual_kernel<false><<<2048, 256>>>(txt, tmp, txt_mod1 + 2 * HIDDEN, out_txt, T_TXT * HIDDEN);

    // ---- img MLP ----
    ln_mod_kernel<<<T_IMG, 256>>>(out_img, img_mod2, xm);
    launch_gemm(xm, img_mlp_w1, img_mlp_b1, hbuf, T_IMG, MLPD, HIDDEN,
                HIDDEN, HIDDEN, MLPD, 0, 0, 0, 1, 1.0f, 1);
    launch_gemm(hbuf, img_mlp_w2, img_mlp_b2, tmp, T_IMG, HIDDEN, MLPD,
                MLPD, MLPD, HIDDEN, 0, 0, 0, 1, 1.0f, 0);
    residual_kernel<false><<<4096, 256>>>(out_img, tmp, img_mod2 + 2 * HIDDEN, out_img, T_IMG * HIDDEN);

    // ---- txt MLP (final residual fused with clip) ----
    ln_mod_kernel<<<T_TXT, 256>>>(out_txt, txt_mod2, xm);
    launch_gemm(xm, txt_mlp_w1, txt_mlp_b1, hbuf, T_TXT, MLPD, HIDDEN,
                HIDDEN, HIDDEN, MLPD, 0, 0, 0, 1, 1.0f, 1);
    launch_gemm(hbuf, txt_mlp_w2, txt_mlp_b2, tmp, T_TXT, HIDDEN, MLPD,
                MLPD, MLPD, HIDDEN, 0, 0, 0, 1, 1.0f, 0);
    residual_kernel<true><<<2048, 256>>>(out_txt, tmp, txt_mod2 + 2 * HIDDEN, out_txt, T_TXT * HIDDEN);
}